// round 3
// baseline (speedup 1.0000x reference)
#include <cuda_runtime.h>
#include <cuda_bf16.h>
#include <cstdint>

// ============================================================================
// out[m][n] = exp(-max(||x_m||^2 + ||y_n||^2 - 2 x_m.y_n, 0))
// x,y: (8192, 256) fp32 ; out: (8192, 8192) fp32
// Legacy HMMA path (mma.sync bf16) — tcgen05 not available under compute_103.
// ============================================================================

#define ROWS 8192
#define DIM  256
#define TILE_M 128
#define TILE_N 256

// smem row stride: 256 + 8 bf16 pad -> 528 B == 132 words == 4 banks (mod 32)
// => conflict-free LDS.32 fragment loads and STS.128 tile fills.
#define SSTRIDE 264

// ---------------- device scratch (no allocations allowed) ------------------
__device__ __nv_bfloat16 g_xb[ROWS * DIM];
__device__ __nv_bfloat16 g_yb[ROWS * DIM];
__device__ float g_xsq[ROWS];
__device__ float g_ysq[ROWS];

// ---------------- smem layout ----------------------------------------------
static constexpr int SMEM_A_OFF = 0;
static constexpr int SMEM_B_OFF = TILE_M * SSTRIDE * 2;               // 67584
static constexpr int SMEM_YSQ   = SMEM_B_OFF + TILE_N * SSTRIDE * 2;  // 202752
static constexpr int SMEM_TOTAL = SMEM_YSQ + TILE_N * 4;              // 203776

// ---------------- prep: fp32 -> bf16 + row norms (1 warp per row) ----------
__global__ void __launch_bounds__(256) cvt_kernel(
    const float* __restrict__ x, const float* __restrict__ y
) {
    int gw  = blockIdx.x * 8 + (threadIdx.x >> 5);   // global row 0..16383
    int lid = threadIdx.x & 31;
    const float* src;
    __nv_bfloat16* dst;
    float* sq;
    int r;
    if (gw < ROWS) { r = gw;        src = x; dst = g_xb; sq = g_xsq; }
    else           { r = gw - ROWS; src = y; dst = g_yb; sq = g_ysq; }
    src += (size_t)r * DIM;
    dst += (size_t)r * DIM;

    float4 v0 = reinterpret_cast<const float4*>(src)[lid];
    float4 v1 = reinterpret_cast<const float4*>(src)[lid + 32];

    float p = v0.x * v0.x + v0.y * v0.y + v0.z * v0.z + v0.w * v0.w
            + v1.x * v1.x + v1.y * v1.y + v1.z * v1.z + v1.w * v1.w;
    #pragma unroll
    for (int off = 16; off > 0; off >>= 1)
        p += __shfl_xor_sync(0xFFFFFFFFu, p, off);

    __nv_bfloat162 b0 = __floats2bfloat162_rn(v0.x, v0.y);
    __nv_bfloat162 b1 = __floats2bfloat162_rn(v0.z, v0.w);
    __nv_bfloat162 b2 = __floats2bfloat162_rn(v1.x, v1.y);
    __nv_bfloat162 b3 = __floats2bfloat162_rn(v1.z, v1.w);
    uint2 pk0, pk1;
    pk0.x = *reinterpret_cast<uint32_t*>(&b0);
    pk0.y = *reinterpret_cast<uint32_t*>(&b1);
    pk1.x = *reinterpret_cast<uint32_t*>(&b2);
    pk1.y = *reinterpret_cast<uint32_t*>(&b3);
    reinterpret_cast<uint2*>(dst)[lid]      = pk0;
    reinterpret_cast<uint2*>(dst)[lid + 32] = pk1;

    if (lid == 0) sq[r] = p;
}

// ---------------- main GEMM + fused RBF epilogue ----------------------------
__device__ __forceinline__ void mma_bf16(
    float c[4], uint32_t a0, uint32_t a1, uint32_t a2, uint32_t a3,
    uint32_t b0, uint32_t b1
) {
    asm volatile(
        "mma.sync.aligned.m16n8k16.row.col.f32.bf16.bf16.f32 "
        "{%0,%1,%2,%3}, {%4,%5,%6,%7}, {%8,%9}, {%0,%1,%2,%3};"
        : "+f"(c[0]), "+f"(c[1]), "+f"(c[2]), "+f"(c[3])
        : "r"(a0), "r"(a1), "r"(a2), "r"(a3), "r"(b0), "r"(b1));
}

__global__ void __launch_bounds__(256, 1) rbf_gemm_kernel(float* __restrict__ out) {
    extern __shared__ __align__(16) char smem[];
    __nv_bfloat16* sA = reinterpret_cast<__nv_bfloat16*>(smem + SMEM_A_OFF);
    __nv_bfloat16* sB = reinterpret_cast<__nv_bfloat16*>(smem + SMEM_B_OFF);
    float* ysq_s      = reinterpret_cast<float*>(smem + SMEM_YSQ);

    const int tid = threadIdx.x;
    const int wid = tid >> 5;
    const int lid = tid & 31;
    const int gid = lid >> 2;   // group id 0..7
    const int tq  = lid & 3;    // thread-in-group 0..3

    const int wm = wid >> 2;    // 0..1 : warp M offset /64
    const int wn = wid & 3;     // 0..3 : warp N offset /64

    const int m0 = blockIdx.y * TILE_M;
    const int n0 = blockIdx.x * TILE_N;

    // ---- fill A tile: 128 rows x 256 cols (each warp fills whole rows) ----
    {
        const uint4* ga = reinterpret_cast<const uint4*>(g_xb + (size_t)m0 * DIM);
        #pragma unroll
        for (int i = 0; i < 16; i++) {
            int row = i * 8 + wid;          // warp w handles row i*8+w
            uint4 v = ga[row * (DIM / 8) + lid];
            *reinterpret_cast<uint4*>(sA + row * SSTRIDE + lid * 8) = v;
        }
    }
    // ---- fill B tile: 256 rows x 256 cols ----
    {
        const uint4* gb = reinterpret_cast<const uint4*>(g_yb + (size_t)n0 * DIM);
        #pragma unroll
        for (int i = 0; i < 32; i++) {
            int row = i * 8 + wid;
            uint4 v = gb[row * (DIM / 8) + lid];
            *reinterpret_cast<uint4*>(sB + row * SSTRIDE + lid * 8) = v;
        }
    }
    // ---- y norms for this tile ----
    ysq_s[tid] = g_ysq[n0 + tid];
    __syncthreads();

    // ---- register tiles -----------------------------------------------------
    float acc[4][8][4];
    #pragma unroll
    for (int mt = 0; mt < 4; mt++)
        #pragma unroll
        for (int nt = 0; nt < 8; nt++)
            #pragma unroll
            for (int j = 0; j < 4; j++) acc[mt][nt][j] = 0.0f;

    const char* aBase = reinterpret_cast<const char*>(sA)
                      + (wm * 64 + gid) * (SSTRIDE * 2) + tq * 4;
    const char* bBase = reinterpret_cast<const char*>(sB)
                      + (wn * 64 + gid) * (SSTRIDE * 2) + tq * 4;

    #pragma unroll 2
    for (int ks = 0; ks < 16; ks++) {
        const int kb = ks * 32;   // 16 bf16 = 32 bytes per k-step

        uint32_t a[4][4];
        #pragma unroll
        for (int mt = 0; mt < 4; mt++) {
            const char* p = aBase + mt * 16 * (SSTRIDE * 2) + kb;
            a[mt][0] = *reinterpret_cast<const uint32_t*>(p);
            a[mt][1] = *reinterpret_cast<const uint32_t*>(p + 8 * SSTRIDE * 2);
            a[mt][2] = *reinterpret_cast<const uint32_t*>(p + 16);
            a[mt][3] = *reinterpret_cast<const uint32_t*>(p + 8 * SSTRIDE * 2 + 16);
        }
        uint32_t b[8][2];
        #pragma unroll
        for (int nt = 0; nt < 8; nt++) {
            const char* p = bBase + nt * 8 * (SSTRIDE * 2) + kb;
            b[nt][0] = *reinterpret_cast<const uint32_t*>(p);
            b[nt][1] = *reinterpret_cast<const uint32_t*>(p + 16);
        }
        #pragma unroll
        for (int mt = 0; mt < 4; mt++)
            #pragma unroll
            for (int nt = 0; nt < 8; nt++)
                mma_bf16(acc[mt][nt], a[mt][0], a[mt][1], a[mt][2], a[mt][3],
                         b[nt][0], b[nt][1]);
    }

    // ---- fused epilogue: d = max(xs + ys - 2c, 0); out = exp(-d) -----------
    const int mrow0 = wm * 64 + gid;          // local row of c0/c1
    const float xs0 = g_xsq[m0 + mrow0];
    const float xs8 = g_xsq[m0 + mrow0 + 8];

    #pragma unroll
    for (int mt = 0; mt < 4; mt++) {
        const int r0 = mrow0 + mt * 16;
        const float xsa = (mt == 0) ? xs0 : g_xsq[m0 + r0];
        const float xsb = (mt == 0) ? xs8 : g_xsq[m0 + r0 + 8];
        float* o0 = out + (size_t)(m0 + r0) * ROWS + n0;
        float* o1 = out + (size_t)(m0 + r0 + 8) * ROWS + n0;
        #pragma unroll
        for (int nt = 0; nt < 8; nt++) {
            const int c = wn * 64 + nt * 8 + tq * 2;
            float ys0 = ysq_s[c];
            float ys1 = ysq_s[c + 1];
            float d0 = fmaxf(xsa + ys0 - 2.0f * acc[mt][nt][0], 0.0f);
            float d1 = fmaxf(xsa + ys1 - 2.0f * acc[mt][nt][1], 0.0f);
            float d2 = fmaxf(xsb + ys0 - 2.0f * acc[mt][nt][2], 0.0f);
            float d3 = fmaxf(xsb + ys1 - 2.0f * acc[mt][nt][3], 0.0f);
            float2 e0, e1;
            e0.x = __expf(-d0); e0.y = __expf(-d1);
            e1.x = __expf(-d2); e1.y = __expf(-d3);
            *reinterpret_cast<float2*>(o0 + c) = e0;
            *reinterpret_cast<float2*>(o1 + c) = e1;
        }
    }
}

// ---------------- launch ----------------------------------------------------
extern "C" void kernel_launch(void* const* d_in, const int* in_sizes, int n_in,
                              void* d_out, int out_size) {
    const float* x = (const float*)d_in[0];
    const float* y = (const float*)d_in[1];
    float* out = (float*)d_out;

    cudaFuncSetAttribute(rbf_gemm_kernel,
                         cudaFuncAttributeMaxDynamicSharedMemorySize, SMEM_TOTAL);

    cvt_kernel<<<2 * ROWS / 8, 256>>>(x, y);
    dim3 grid(ROWS / TILE_N, ROWS / TILE_M);   // (32, 64)
    rbf_gemm_kernel<<<grid, 256, SMEM_TOTAL>>>(out);
}

// round 4
// speedup vs baseline: 1.0024x; 1.0024x over previous
#include <cuda_runtime.h>
#include <cuda_bf16.h>
#include <cstdint>

// ============================================================================
// out[m][n] = exp(-max(||x_m||^2 + ||y_n||^2 - 2 x_m.y_n, 0))
// x,y: (8192, 256) fp32 ; out: (8192, 8192) fp32
// HMMA (mma.sync bf16) + cp.async double-buffered K-pipeline + ldmatrix.
// ============================================================================

#define ROWS 8192
#define DIM  256
#define TILE_M 128
#define TILE_N 256
#define KC 64                    // k-chunk (bf16 elements)
#define NCHUNK (DIM / KC)        // 4

// smem row stride for a KC-wide chunk: 64 + 8 pad = 72 bf16 = 144 B
// 144 B == 36 words == 4 banks (mod 32) -> conflict-free ldmatrix / STS.
#define SSTR 72

// ---------------- device scratch (no allocations allowed) ------------------
__device__ __nv_bfloat16 g_xb[ROWS * DIM];
__device__ __nv_bfloat16 g_yb[ROWS * DIM];
__device__ float g_xsq[ROWS];
__device__ float g_ysq[ROWS];

// ---------------- smem layout ----------------------------------------------
static constexpr int A_BYTES   = TILE_M * SSTR * 2;          // 18432
static constexpr int B_BYTES   = TILE_N * SSTR * 2;          // 36864
static constexpr int STAGE     = A_BYTES + B_BYTES;          // 55296
static constexpr int SMEM_YSQ  = 2 * STAGE;                  // 110592
static constexpr int SMEM_TOTAL = SMEM_YSQ + TILE_N * 4;     // 111616

// ---------------- PTX helpers ----------------------------------------------
__device__ __forceinline__ uint32_t smem_to_u32(const void* p) {
    uint32_t a;
    asm("{ .reg .u64 t; cvta.to.shared.u64 t, %1; cvt.u32.u64 %0, t; }"
        : "=r"(a) : "l"(p));
    return a;
}

__device__ __forceinline__ void cp_async16(uint32_t dst, const void* src) {
    asm volatile("cp.async.cg.shared.global [%0], [%1], 16;"
                 :: "r"(dst), "l"(src) : "memory");
}
#define CP_COMMIT() asm volatile("cp.async.commit_group;" ::: "memory")
#define CP_WAIT(n)  asm volatile("cp.async.wait_group %0;" :: "n"(n) : "memory")

__device__ __forceinline__ void ldm_x4(uint32_t r[4], uint32_t addr) {
    asm volatile("ldmatrix.sync.aligned.m8n8.x4.shared.b16 {%0,%1,%2,%3}, [%4];"
                 : "=r"(r[0]), "=r"(r[1]), "=r"(r[2]), "=r"(r[3]) : "r"(addr));
}

__device__ __forceinline__ void mma_bf16(
    float c[4], const uint32_t a[4], uint32_t b0, uint32_t b1
) {
    asm volatile(
        "mma.sync.aligned.m16n8k16.row.col.f32.bf16.bf16.f32 "
        "{%0,%1,%2,%3}, {%4,%5,%6,%7}, {%8,%9}, {%0,%1,%2,%3};"
        : "+f"(c[0]), "+f"(c[1]), "+f"(c[2]), "+f"(c[3])
        : "r"(a[0]), "r"(a[1]), "r"(a[2]), "r"(a[3]), "r"(b0), "r"(b1));
}

// ---------------- prep: fp32 -> bf16 + row norms (1 warp per row) ----------
__global__ void __launch_bounds__(256) cvt_kernel(
    const float* __restrict__ x, const float* __restrict__ y
) {
    int gw  = blockIdx.x * 8 + (threadIdx.x >> 5);
    int lid = threadIdx.x & 31;
    const float* src;
    __nv_bfloat16* dst;
    float* sq;
    int r;
    if (gw < ROWS) { r = gw;        src = x; dst = g_xb; sq = g_xsq; }
    else           { r = gw - ROWS; src = y; dst = g_yb; sq = g_ysq; }
    src += (size_t)r * DIM;
    dst += (size_t)r * DIM;

    float4 v0 = reinterpret_cast<const float4*>(src)[lid];
    float4 v1 = reinterpret_cast<const float4*>(src)[lid + 32];

    float p = v0.x * v0.x + v0.y * v0.y + v0.z * v0.z + v0.w * v0.w
            + v1.x * v1.x + v1.y * v1.y + v1.z * v1.z + v1.w * v1.w;
    #pragma unroll
    for (int off = 16; off > 0; off >>= 1)
        p += __shfl_xor_sync(0xFFFFFFFFu, p, off);

    __nv_bfloat162 b0 = __floats2bfloat162_rn(v0.x, v0.y);
    __nv_bfloat162 b1 = __floats2bfloat162_rn(v0.z, v0.w);
    __nv_bfloat162 b2 = __floats2bfloat162_rn(v1.x, v1.y);
    __nv_bfloat162 b3 = __floats2bfloat162_rn(v1.z, v1.w);
    uint2 pk0, pk1;
    pk0.x = *reinterpret_cast<uint32_t*>(&b0);
    pk0.y = *reinterpret_cast<uint32_t*>(&b1);
    pk1.x = *reinterpret_cast<uint32_t*>(&b2);
    pk1.y = *reinterpret_cast<uint32_t*>(&b3);
    reinterpret_cast<uint2*>(dst)[lid]      = pk0;
    reinterpret_cast<uint2*>(dst)[lid + 32] = pk1;

    if (lid == 0) sq[r] = p;
}

// ---------------- main GEMM + fused RBF epilogue ----------------------------
__global__ void __launch_bounds__(256, 1) rbf_gemm_kernel(float* __restrict__ out) {
    extern __shared__ __align__(128) char smem[];
    const uint32_t sbase = smem_to_u32(smem);
    float* ysq_s = reinterpret_cast<float*>(smem + SMEM_YSQ);

    const int tid = threadIdx.x;
    const int wid = tid >> 5;
    const int lid = tid & 31;
    const int gid = lid >> 2;
    const int tq  = lid & 3;
    const int wm  = wid >> 2;    // 0..1
    const int wn  = wid & 3;     // 0..3

    const int m0 = blockIdx.y * TILE_M;
    const int n0 = blockIdx.x * TILE_N;

    ysq_s[tid] = g_ysq[n0 + tid];

    // ---- cp.async chunk loader --------------------------------------------
    const char* gA = reinterpret_cast<const char*>(g_xb + (size_t)m0 * DIM);
    const char* gB = reinterpret_cast<const char*>(g_yb + (size_t)n0 * DIM);

    auto load_chunk = [&](int c, int st) {
        const char* ga = gA + c * (KC * 2);      // 128B col window
        uint32_t da = sbase + st * STAGE;
        #pragma unroll
        for (int i = 0; i < 4; i++) {            // A: 128 rows x 8 x 16B
            int idx = i * 256 + tid;
            int row = idx >> 3, col = idx & 7;
            cp_async16(da + row * (SSTR * 2) + col * 16,
                       ga + (size_t)row * (DIM * 2) + col * 16);
        }
        const char* gb = gB + c * (KC * 2);
        uint32_t db = sbase + st * STAGE + A_BYTES;
        #pragma unroll
        for (int i = 0; i < 8; i++) {            // B: 256 rows x 8 x 16B
            int idx = i * 256 + tid;
            int row = idx >> 3, col = idx & 7;
            cp_async16(db + row * (SSTR * 2) + col * 16,
                       gb + (size_t)row * (DIM * 2) + col * 16);
        }
    };

    // ---- per-thread ldmatrix base addresses ---------------------------------
    // x4 matrix order: m0 rows+0/k+0, m1 rows+8/k+0, m2 rows+0/k+8, m3 rows+8/k+8
    const int msel = lid >> 3, mrow = lid & 7;
    const int roff = (msel & 1) * 8;
    const int koff = (msel >> 1) * 8;
    const uint32_t aAddr = sbase +
        (uint32_t)(((wm * 64 + roff + mrow) * SSTR + koff) * 2);
    const uint32_t bAddr = sbase + A_BYTES +
        (uint32_t)(((wn * 64 + roff + mrow) * SSTR + koff) * 2);

    float acc[4][8][4];
    #pragma unroll
    for (int mt = 0; mt < 4; mt++)
        #pragma unroll
        for (int nt = 0; nt < 8; nt++)
            #pragma unroll
            for (int j = 0; j < 4; j++) acc[mt][nt][j] = 0.0f;

    // ---- compute one KC=64 chunk (4 k-steps of 16) --------------------------
    auto compute = [&](int st) {
        const uint32_t so = st * STAGE;
        #pragma unroll
        for (int ksl = 0; ksl < 4; ksl++) {
            uint32_t a[4][4];
            #pragma unroll
            for (int mt = 0; mt < 4; mt++)
                ldm_x4(a[mt], aAddr + so +
                       (uint32_t)((mt * 16 * SSTR + ksl * 16) * 2));
            uint32_t b[4][4];
            #pragma unroll
            for (int np = 0; np < 4; np++)
                ldm_x4(b[np], bAddr + so +
                       (uint32_t)((np * 16 * SSTR + ksl * 16) * 2));
            #pragma unroll
            for (int mt = 0; mt < 4; mt++) {
                #pragma unroll
                for (int np = 0; np < 4; np++) {
                    mma_bf16(acc[mt][2 * np],     a[mt], b[np][0], b[np][2]);
                    mma_bf16(acc[mt][2 * np + 1], a[mt], b[np][1], b[np][3]);
                }
            }
        }
    };

    // ---- 2-stage software pipeline over 4 chunks -----------------------------
    load_chunk(0, 0); CP_COMMIT();
    load_chunk(1, 1); CP_COMMIT();
    CP_WAIT(1); __syncthreads();
    compute(0); __syncthreads();
    load_chunk(2, 0); CP_COMMIT();
    CP_WAIT(1); __syncthreads();
    compute(1); __syncthreads();
    load_chunk(3, 1); CP_COMMIT();
    CP_WAIT(1); __syncthreads();
    compute(0); __syncthreads();
    CP_WAIT(0); __syncthreads();
    compute(1);

    // ---- fused epilogue: d = max(xs + ys - 2c, 0); out = exp(-d) -----------
    const int mrow0 = wm * 64 + gid;
    #pragma unroll
    for (int mt = 0; mt < 4; mt++) {
        const int r0 = mrow0 + mt * 16;
        const float xsa = g_xsq[m0 + r0];
        const float xsb = g_xsq[m0 + r0 + 8];
        float* o0 = out + (size_t)(m0 + r0) * ROWS + n0;
        float* o1 = out + (size_t)(m0 + r0 + 8) * ROWS + n0;
        #pragma unroll
        for (int nt = 0; nt < 8; nt++) {
            const int c = wn * 64 + nt * 8 + tq * 2;
            float ys0 = ysq_s[c];
            float ys1 = ysq_s[c + 1];
            float d0 = fmaxf(xsa + ys0 - 2.0f * acc[mt][nt][0], 0.0f);
            float d1 = fmaxf(xsa + ys1 - 2.0f * acc[mt][nt][1], 0.0f);
            float d2 = fmaxf(xsb + ys0 - 2.0f * acc[mt][nt][2], 0.0f);
            float d3 = fmaxf(xsb + ys1 - 2.0f * acc[mt][nt][3], 0.0f);
            float2 e0, e1;
            e0.x = __expf(-d0); e0.y = __expf(-d1);
            e1.x = __expf(-d2); e1.y = __expf(-d3);
            *reinterpret_cast<float2*>(o0 + c) = e0;
            *reinterpret_cast<float2*>(o1 + c) = e1;
        }
    }
}

// ---------------- launch ----------------------------------------------------
extern "C" void kernel_launch(void* const* d_in, const int* in_sizes, int n_in,
                              void* d_out, int out_size) {
    const float* x = (const float*)d_in[0];
    const float* y = (const float*)d_in[1];
    float* out = (float*)d_out;

    cudaFuncSetAttribute(rbf_gemm_kernel,
                         cudaFuncAttributeMaxDynamicSharedMemorySize, SMEM_TOTAL);

    cvt_kernel<<<2 * ROWS / 8, 256>>>(x, y);
    dim3 grid(ROWS / TILE_N, ROWS / TILE_M);   // (32, 64)
    rbf_gemm_kernel<<<grid, 256, SMEM_TOTAL>>>(out);
}

// round 5
// speedup vs baseline: 1.0535x; 1.0509x over previous
#include <cuda_runtime.h>
#include <cuda_bf16.h>
#include <cstdint>

// ============================================================================
// out[m][n] = exp(-max(||x_m||^2 + ||y_n||^2 - 2 x_m.y_n, 0))
// x,y: (8192, 256) fp32 ; out: (8192, 8192) fp32
// HMMA (mma.sync bf16), cp.async 2-stage K-pipeline, ldmatrix, 2 CTAs/SM.
// ============================================================================

#define ROWS 8192
#define DIM  256
#define TILE_M 128
#define TILE_N 128
#define KC 64                    // k-chunk (bf16 elements)

// smem row stride for a KC-wide chunk: 64 + 8 pad = 72 bf16 = 144 B
// 144 B == 36 words == 4 banks (mod 32) -> conflict-free ldmatrix / STS.
#define SSTR 72

// ---------------- device scratch (no allocations allowed) ------------------
__device__ __nv_bfloat16 g_xb[ROWS * DIM];
__device__ __nv_bfloat16 g_yb[ROWS * DIM];
__device__ float g_xsq[ROWS];
__device__ float g_ysq[ROWS];

// ---------------- smem layout ----------------------------------------------
static constexpr int A_BYTES    = TILE_M * SSTR * 2;          // 18432
static constexpr int B_BYTES    = TILE_N * SSTR * 2;          // 18432
static constexpr int STAGE      = A_BYTES + B_BYTES;          // 36864
static constexpr int SMEM_YSQ   = 2 * STAGE;                  // 73728
static constexpr int SMEM_TOTAL = SMEM_YSQ + TILE_N * 4;      // 74240

// ---------------- PTX helpers ----------------------------------------------
__device__ __forceinline__ uint32_t smem_to_u32(const void* p) {
    uint32_t a;
    asm("{ .reg .u64 t; cvta.to.shared.u64 t, %1; cvt.u32.u64 %0, t; }"
        : "=r"(a) : "l"(p));
    return a;
}

__device__ __forceinline__ void cp_async16(uint32_t dst, const void* src) {
    asm volatile("cp.async.cg.shared.global [%0], [%1], 16;"
                 :: "r"(dst), "l"(src) : "memory");
}
#define CP_COMMIT() asm volatile("cp.async.commit_group;" ::: "memory")
#define CP_WAIT(n)  asm volatile("cp.async.wait_group %0;" :: "n"(n) : "memory")

__device__ __forceinline__ void ldm_x4(uint32_t r[4], uint32_t addr) {
    asm volatile("ldmatrix.sync.aligned.m8n8.x4.shared.b16 {%0,%1,%2,%3}, [%4];"
                 : "=r"(r[0]), "=r"(r[1]), "=r"(r[2]), "=r"(r[3]) : "r"(addr));
}

__device__ __forceinline__ void mma_bf16(
    float c[4], const uint32_t a[4], uint32_t b0, uint32_t b1
) {
    asm volatile(
        "mma.sync.aligned.m16n8k16.row.col.f32.bf16.bf16.f32 "
        "{%0,%1,%2,%3}, {%4,%5,%6,%7}, {%8,%9}, {%0,%1,%2,%3};"
        : "+f"(c[0]), "+f"(c[1]), "+f"(c[2]), "+f"(c[3])
        : "r"(a[0]), "r"(a[1]), "r"(a[2]), "r"(a[3]), "r"(b0), "r"(b1));
}

// ---------------- prep: fp32 -> bf16 + row norms (1 warp per row) ----------
__global__ void __launch_bounds__(256) cvt_kernel(
    const float* __restrict__ x, const float* __restrict__ y
) {
    int gw  = blockIdx.x * 8 + (threadIdx.x >> 5);
    int lid = threadIdx.x & 31;
    const float* src;
    __nv_bfloat16* dst;
    float* sq;
    int r;
    if (gw < ROWS) { r = gw;        src = x; dst = g_xb; sq = g_xsq; }
    else           { r = gw - ROWS; src = y; dst = g_yb; sq = g_ysq; }
    src += (size_t)r * DIM;
    dst += (size_t)r * DIM;

    float4 v0 = reinterpret_cast<const float4*>(src)[lid];
    float4 v1 = reinterpret_cast<const float4*>(src)[lid + 32];

    float p = v0.x * v0.x + v0.y * v0.y + v0.z * v0.z + v0.w * v0.w
            + v1.x * v1.x + v1.y * v1.y + v1.z * v1.z + v1.w * v1.w;
    #pragma unroll
    for (int off = 16; off > 0; off >>= 1)
        p += __shfl_xor_sync(0xFFFFFFFFu, p, off);

    __nv_bfloat162 b0 = __floats2bfloat162_rn(v0.x, v0.y);
    __nv_bfloat162 b1 = __floats2bfloat162_rn(v0.z, v0.w);
    __nv_bfloat162 b2 = __floats2bfloat162_rn(v1.x, v1.y);
    __nv_bfloat162 b3 = __floats2bfloat162_rn(v1.z, v1.w);
    uint2 pk0, pk1;
    pk0.x = *reinterpret_cast<uint32_t*>(&b0);
    pk0.y = *reinterpret_cast<uint32_t*>(&b1);
    pk1.x = *reinterpret_cast<uint32_t*>(&b2);
    pk1.y = *reinterpret_cast<uint32_t*>(&b3);
    reinterpret_cast<uint2*>(dst)[lid]      = pk0;
    reinterpret_cast<uint2*>(dst)[lid + 32] = pk1;

    if (lid == 0) sq[r] = p;
}

// ---------------- main GEMM + fused RBF epilogue ----------------------------
// 128 threads (4 warps in 2x2), warp tile 64x64, 2 CTAs per SM.
__global__ void __launch_bounds__(128, 2) rbf_gemm_kernel(float* __restrict__ out) {
    extern __shared__ __align__(128) char smem[];
    const uint32_t sbase = smem_to_u32(smem);
    float* ysq_s = reinterpret_cast<float*>(smem + SMEM_YSQ);

    const int tid = threadIdx.x;
    const int wid = tid >> 5;
    const int lid = tid & 31;
    const int gid = lid >> 2;
    const int tq  = lid & 3;
    const int wm  = wid >> 1;    // 0..1
    const int wn  = wid & 1;     // 0..1

    const int m0 = blockIdx.y * TILE_M;
    const int n0 = blockIdx.x * TILE_N;

    ysq_s[tid] = g_ysq[n0 + tid];

    // ---- cp.async chunk loader --------------------------------------------
    const char* gA = reinterpret_cast<const char*>(g_xb + (size_t)m0 * DIM);
    const char* gB = reinterpret_cast<const char*>(g_yb + (size_t)n0 * DIM);

    auto load_chunk = [&](int c, int st) {
        const char* ga = gA + c * (KC * 2);      // 128B col window
        uint32_t da = sbase + st * STAGE;
        #pragma unroll
        for (int i = 0; i < 8; i++) {            // A: 128 rows x 8 x 16B
            int idx = i * 128 + tid;
            int row = idx >> 3, col = idx & 7;
            cp_async16(da + row * (SSTR * 2) + col * 16,
                       ga + (size_t)row * (DIM * 2) + col * 16);
        }
        const char* gb = gB + c * (KC * 2);
        uint32_t db = sbase + st * STAGE + A_BYTES;
        #pragma unroll
        for (int i = 0; i < 8; i++) {            // B: 128 rows x 8 x 16B
            int idx = i * 128 + tid;
            int row = idx >> 3, col = idx & 7;
            cp_async16(db + row * (SSTR * 2) + col * 16,
                       gb + (size_t)row * (DIM * 2) + col * 16);
        }
    };

    // ---- per-thread ldmatrix base addresses ---------------------------------
    const int msel = lid >> 3, mrow = lid & 7;
    const int roff = (msel & 1) * 8;
    const int koff = (msel >> 1) * 8;
    const uint32_t aAddr = sbase +
        (uint32_t)(((wm * 64 + roff + mrow) * SSTR + koff) * 2);
    const uint32_t bAddr = sbase + A_BYTES +
        (uint32_t)(((wn * 64 + roff + mrow) * SSTR + koff) * 2);

    float acc[4][8][4];
    #pragma unroll
    for (int mt = 0; mt < 4; mt++)
        #pragma unroll
        for (int nt = 0; nt < 8; nt++)
            #pragma unroll
            for (int j = 0; j < 4; j++) acc[mt][nt][j] = 0.0f;

    // ---- compute one KC=64 chunk (4 k-steps of 16) --------------------------
    auto compute = [&](int st) {
        const uint32_t so = st * STAGE;
        #pragma unroll
        for (int ksl = 0; ksl < 4; ksl++) {
            uint32_t a[4][4];
            #pragma unroll
            for (int mt = 0; mt < 4; mt++)
                ldm_x4(a[mt], aAddr + so +
                       (uint32_t)((mt * 16 * SSTR + ksl * 16) * 2));
            uint32_t b[4][4];
            #pragma unroll
            for (int np = 0; np < 4; np++)
                ldm_x4(b[np], bAddr + so +
                       (uint32_t)((np * 16 * SSTR + ksl * 16) * 2));
            #pragma unroll
            for (int mt = 0; mt < 4; mt++) {
                #pragma unroll
                for (int np = 0; np < 4; np++) {
                    mma_bf16(acc[mt][2 * np],     a[mt], b[np][0], b[np][2]);
                    mma_bf16(acc[mt][2 * np + 1], a[mt], b[np][1], b[np][3]);
                }
            }
        }
    };

    // ---- 2-stage software pipeline over 4 chunks -----------------------------
    load_chunk(0, 0); CP_COMMIT();
    load_chunk(1, 1); CP_COMMIT();
    CP_WAIT(1); __syncthreads();
    compute(0); __syncthreads();
    load_chunk(2, 0); CP_COMMIT();
    CP_WAIT(1); __syncthreads();
    compute(1); __syncthreads();
    load_chunk(3, 1); CP_COMMIT();
    CP_WAIT(1); __syncthreads();
    compute(0); __syncthreads();
    CP_WAIT(0); __syncthreads();
    compute(1);

    // ---- fused epilogue: d = max(xs + ys - 2c, 0); out = exp(-d) -----------
    const int mrow0 = wm * 64 + gid;
    #pragma unroll
    for (int mt = 0; mt < 4; mt++) {
        const int r0 = mrow0 + mt * 16;
        const float xsa = g_xsq[m0 + r0];
        const float xsb = g_xsq[m0 + r0 + 8];
        float* o0 = out + (size_t)(m0 + r0) * ROWS + n0;
        float* o1 = out + (size_t)(m0 + r0 + 8) * ROWS + n0;
        #pragma unroll
        for (int nt = 0; nt < 8; nt++) {
            const int c = wn * 64 + nt * 8 + tq * 2;
            float ys0 = ysq_s[c];
            float ys1 = ysq_s[c + 1];
            float d0 = fmaxf(xsa + ys0 - 2.0f * acc[mt][nt][0], 0.0f);
            float d1 = fmaxf(xsa + ys1 - 2.0f * acc[mt][nt][1], 0.0f);
            float d2 = fmaxf(xsb + ys0 - 2.0f * acc[mt][nt][2], 0.0f);
            float d3 = fmaxf(xsb + ys1 - 2.0f * acc[mt][nt][3], 0.0f);
            float2 e0, e1;
            e0.x = __expf(-d0); e0.y = __expf(-d1);
            e1.x = __expf(-d2); e1.y = __expf(-d3);
            *reinterpret_cast<float2*>(o0 + c) = e0;
            *reinterpret_cast<float2*>(o1 + c) = e1;
        }
    }
}

// ---------------- launch ----------------------------------------------------
extern "C" void kernel_launch(void* const* d_in, const int* in_sizes, int n_in,
                              void* d_out, int out_size) {
    const float* x = (const float*)d_in[0];
    const float* y = (const float*)d_in[1];
    float* out = (float*)d_out;

    cudaFuncSetAttribute(rbf_gemm_kernel,
                         cudaFuncAttributeMaxDynamicSharedMemorySize, SMEM_TOTAL);

    cvt_kernel<<<2 * ROWS / 8, 256>>>(x, y);
    dim3 grid(ROWS / TILE_N, ROWS / TILE_M);   // (64, 64)
    rbf_gemm_kernel<<<grid, 128, SMEM_TOTAL>>>(out);
}

// round 6
// speedup vs baseline: 1.2000x; 1.1391x over previous
#include <cuda_runtime.h>
#include <cuda_fp16.h>
#include <cstdint>

// ============================================================================
// out[m][n] = exp(-max(||x_m||^2 + ||y_n||^2 - 2 x_m.y_n, 0))
// x,y: (8192, 256) fp32 ; out: (8192, 8192) fp32
// f16 HMMA (f16 accumulate), cp.async 2-stage K-pipeline, ldmatrix, 3 CTAs/SM.
// ============================================================================

#define ROWS 8192
#define DIM  256
#define TILE_M 128
#define TILE_N 128
#define KC 64                    // k-chunk (f16 elements)

// smem row stride for a KC-wide chunk: 64 + 8 pad = 72 f16 = 144 B
// 144 B == 36 words == 4 banks (mod 32) -> conflict-free ldmatrix / STS.
#define SSTR 72

// ---------------- device scratch (no allocations allowed) ------------------
__device__ __half g_xh[ROWS * DIM];
__device__ __half g_yh[ROWS * DIM];
__device__ float g_xsq[ROWS];
__device__ float g_ysq[ROWS];

// ---------------- smem layout ----------------------------------------------
static constexpr int A_BYTES    = TILE_M * SSTR * 2;          // 18432
static constexpr int B_BYTES    = TILE_N * SSTR * 2;          // 18432
static constexpr int STAGE      = A_BYTES + B_BYTES;          // 36864
static constexpr int SMEM_YSQ   = 2 * STAGE;                  // 73728
static constexpr int SMEM_TOTAL = SMEM_YSQ + TILE_N * 4;      // 74240

// ---------------- PTX helpers ----------------------------------------------
__device__ __forceinline__ uint32_t smem_to_u32(const void* p) {
    uint32_t a;
    asm("{ .reg .u64 t; cvta.to.shared.u64 t, %1; cvt.u32.u64 %0, t; }"
        : "=r"(a) : "l"(p));
    return a;
}

__device__ __forceinline__ void cp_async16(uint32_t dst, const void* src) {
    asm volatile("cp.async.cg.shared.global [%0], [%1], 16;"
                 :: "r"(dst), "l"(src) : "memory");
}
#define CP_COMMIT() asm volatile("cp.async.commit_group;" ::: "memory")
#define CP_WAIT(n)  asm volatile("cp.async.wait_group %0;" :: "n"(n) : "memory")

__device__ __forceinline__ void ldm_x4(uint32_t r[4], uint32_t addr) {
    asm volatile("ldmatrix.sync.aligned.m8n8.x4.shared.b16 {%0,%1,%2,%3}, [%4];"
                 : "=r"(r[0]), "=r"(r[1]), "=r"(r[2]), "=r"(r[3]) : "r"(addr));
}

// f16 x f16 -> f16 accumulate: C/D are 2 b32 regs (4 halves).
// c[0] = {row g, col 2q / 2q+1}, c[1] = {row g+8, col 2q / 2q+1}
__device__ __forceinline__ void mma_f16(
    uint32_t c[2], const uint32_t a[4], uint32_t b0, uint32_t b1
) {
    asm volatile(
        "mma.sync.aligned.m16n8k16.row.col.f16.f16.f16.f16 "
        "{%0,%1}, {%2,%3,%4,%5}, {%6,%7}, {%0,%1};"
        : "+r"(c[0]), "+r"(c[1])
        : "r"(a[0]), "r"(a[1]), "r"(a[2]), "r"(a[3]), "r"(b0), "r"(b1));
}

// ---------------- prep: fp32 -> f16 + row norms (1 warp per row) -----------
__global__ void __launch_bounds__(256) cvt_kernel(
    const float* __restrict__ x, const float* __restrict__ y
) {
    int gw  = blockIdx.x * 8 + (threadIdx.x >> 5);
    int lid = threadIdx.x & 31;
    const float* src;
    __half* dst;
    float* sq;
    int r;
    if (gw < ROWS) { r = gw;        src = x; dst = g_xh; sq = g_xsq; }
    else           { r = gw - ROWS; src = y; dst = g_yh; sq = g_ysq; }
    src += (size_t)r * DIM;
    dst += (size_t)r * DIM;

    float4 v0 = reinterpret_cast<const float4*>(src)[lid];
    float4 v1 = reinterpret_cast<const float4*>(src)[lid + 32];

    float p = v0.x * v0.x + v0.y * v0.y + v0.z * v0.z + v0.w * v0.w
            + v1.x * v1.x + v1.y * v1.y + v1.z * v1.z + v1.w * v1.w;
    #pragma unroll
    for (int off = 16; off > 0; off >>= 1)
        p += __shfl_xor_sync(0xFFFFFFFFu, p, off);

    __half2 h0 = __floats2half2_rn(v0.x, v0.y);
    __half2 h1 = __floats2half2_rn(v0.z, v0.w);
    __half2 h2 = __floats2half2_rn(v1.x, v1.y);
    __half2 h3 = __floats2half2_rn(v1.z, v1.w);
    uint2 pk0, pk1;
    pk0.x = *reinterpret_cast<uint32_t*>(&h0);
    pk0.y = *reinterpret_cast<uint32_t*>(&h1);
    pk1.x = *reinterpret_cast<uint32_t*>(&h2);
    pk1.y = *reinterpret_cast<uint32_t*>(&h3);
    reinterpret_cast<uint2*>(dst)[lid]      = pk0;
    reinterpret_cast<uint2*>(dst)[lid + 32] = pk1;

    if (lid == 0) sq[r] = p;
}

// ---------------- main GEMM + fused RBF epilogue ----------------------------
// 128 threads (4 warps in 2x2), warp tile 64x64 (f16 acc), 3 CTAs per SM.
__global__ void __launch_bounds__(128, 3) rbf_gemm_kernel(float* __restrict__ out) {
    extern __shared__ __align__(128) char smem[];
    const uint32_t sbase = smem_to_u32(smem);
    float* ysq_s = reinterpret_cast<float*>(smem + SMEM_YSQ);

    const int tid = threadIdx.x;
    const int wid = tid >> 5;
    const int lid = tid & 31;
    const int gid = lid >> 2;
    const int tq  = lid & 3;
    const int wm  = wid >> 1;    // 0..1
    const int wn  = wid & 1;     // 0..1

    const int m0 = blockIdx.y * TILE_M;
    const int n0 = blockIdx.x * TILE_N;

    ysq_s[tid] = g_ysq[n0 + tid];

    // ---- cp.async chunk loader --------------------------------------------
    const char* gA = reinterpret_cast<const char*>(g_xh + (size_t)m0 * DIM);
    const char* gB = reinterpret_cast<const char*>(g_yh + (size_t)n0 * DIM);

    auto load_chunk = [&](int c, int st) {
        const char* ga = gA + c * (KC * 2);      // 128B col window
        uint32_t da = sbase + st * STAGE;
        #pragma unroll
        for (int i = 0; i < 8; i++) {            // A: 128 rows x 8 x 16B
            int idx = i * 128 + tid;
            int row = idx >> 3, col = idx & 7;
            cp_async16(da + row * (SSTR * 2) + col * 16,
                       ga + (size_t)row * (DIM * 2) + col * 16);
        }
        const char* gb = gB + c * (KC * 2);
        uint32_t db = sbase + st * STAGE + A_BYTES;
        #pragma unroll
        for (int i = 0; i < 8; i++) {            // B: 128 rows x 8 x 16B
            int idx = i * 128 + tid;
            int row = idx >> 3, col = idx & 7;
            cp_async16(db + row * (SSTR * 2) + col * 16,
                       gb + (size_t)row * (DIM * 2) + col * 16);
        }
    };

    // ---- per-thread ldmatrix base addresses ---------------------------------
    const int msel = lid >> 3, mrow = lid & 7;
    const int roff = (msel & 1) * 8;
    const int koff = (msel >> 1) * 8;
    const uint32_t aAddr = sbase +
        (uint32_t)(((wm * 64 + roff + mrow) * SSTR + koff) * 2);
    const uint32_t bAddr = sbase + A_BYTES +
        (uint32_t)(((wn * 64 + roff + mrow) * SSTR + koff) * 2);

    uint32_t acc[4][8][2];
    #pragma unroll
    for (int mt = 0; mt < 4; mt++)
        #pragma unroll
        for (int nt = 0; nt < 8; nt++) {
            acc[mt][nt][0] = 0u;
            acc[mt][nt][1] = 0u;
        }

    // ---- compute one KC=64 chunk (4 k-steps of 16) --------------------------
    auto compute = [&](int st) {
        const uint32_t so = st * STAGE;
        #pragma unroll
        for (int ksl = 0; ksl < 4; ksl++) {
            uint32_t a[4][4];
            #pragma unroll
            for (int mt = 0; mt < 4; mt++)
                ldm_x4(a[mt], aAddr + so +
                       (uint32_t)((mt * 16 * SSTR + ksl * 16) * 2));
            uint32_t b[4][4];
            #pragma unroll
            for (int np = 0; np < 4; np++)
                ldm_x4(b[np], bAddr + so +
                       (uint32_t)((np * 16 * SSTR + ksl * 16) * 2));
            #pragma unroll
            for (int mt = 0; mt < 4; mt++) {
                #pragma unroll
                for (int np = 0; np < 4; np++) {
                    mma_f16(acc[mt][2 * np],     a[mt], b[np][0], b[np][2]);
                    mma_f16(acc[mt][2 * np + 1], a[mt], b[np][1], b[np][3]);
                }
            }
        }
    };

    // ---- 2-stage software pipeline over 4 chunks -----------------------------
    load_chunk(0, 0); CP_COMMIT();
    load_chunk(1, 1); CP_COMMIT();
    CP_WAIT(1); __syncthreads();
    compute(0); __syncthreads();
    load_chunk(2, 0); CP_COMMIT();
    CP_WAIT(1); __syncthreads();
    compute(1); __syncthreads();
    load_chunk(3, 1); CP_COMMIT();
    CP_WAIT(1); __syncthreads();
    compute(0); __syncthreads();
    CP_WAIT(0); __syncthreads();
    compute(1);

    // ---- fused epilogue: d = max(xs + ys - 2c, 0); out = exp(-d) -----------
    const int mrow0 = wm * 64 + gid;
    #pragma unroll
    for (int mt = 0; mt < 4; mt++) {
        const int r0 = mrow0 + mt * 16;
        const float xsa = g_xsq[m0 + r0];
        const float xsb = g_xsq[m0 + r0 + 8];
        float* o0 = out + (size_t)(m0 + r0) * ROWS + n0;
        float* o1 = out + (size_t)(m0 + r0 + 8) * ROWS + n0;
        #pragma unroll
        for (int nt = 0; nt < 8; nt++) {
            const int c = wn * 64 + nt * 8 + tq * 2;
            float ys0 = ysq_s[c];
            float ys1 = ysq_s[c + 1];
            float2 ca = __half22float2(*reinterpret_cast<__half2*>(&acc[mt][nt][0]));
            float2 cb = __half22float2(*reinterpret_cast<__half2*>(&acc[mt][nt][1]));
            float d0 = fmaxf(xsa + ys0 - 2.0f * ca.x, 0.0f);
            float d1 = fmaxf(xsa + ys1 - 2.0f * ca.y, 0.0f);
            float d2 = fmaxf(xsb + ys0 - 2.0f * cb.x, 0.0f);
            float d3 = fmaxf(xsb + ys1 - 2.0f * cb.y, 0.0f);
            float2 e0, e1;
            e0.x = __expf(-d0); e0.y = __expf(-d1);
            e1.x = __expf(-d2); e1.y = __expf(-d3);
            *reinterpret_cast<float2*>(o0 + c) = e0;
            *reinterpret_cast<float2*>(o1 + c) = e1;
        }
    }
}

// ---------------- launch ----------------------------------------------------
extern "C" void kernel_launch(void* const* d_in, const int* in_sizes, int n_in,
                              void* d_out, int out_size) {
    const float* x = (const float*)d_in[0];
    const float* y = (const float*)d_in[1];
    float* out = (float*)d_out;

    cudaFuncSetAttribute(rbf_gemm_kernel,
                         cudaFuncAttributeMaxDynamicSharedMemorySize, SMEM_TOTAL);

    cvt_kernel<<<2 * ROWS / 8, 256>>>(x, y);
    dim3 grid(ROWS / TILE_N, ROWS / TILE_M);   // (64, 64)
    rbf_gemm_kernel<<<grid, 128, SMEM_TOTAL>>>(out);
}